// round 14
// baseline (speedup 1.0000x reference)
#include <cuda_runtime.h>
#include <math.h>

#define BSZ  1024
#define TLEN 256
#define HH   128
#define GG   384   // 3*H

// -------- scratch (static device globals; no runtime allocation) --------
__device__ float g_gi[(size_t)BSZ * TLEN * GG];    // 402 MB, reused for gi0 then gi1
__device__ float g_seq[(size_t)BSZ * TLEN * HH];   // 134 MB, layer-0 output sequence
__device__ float g_hlast[(size_t)BSZ * HH];        // layer-1 final hidden
__device__ float g_wT[2][160 * GG];                // W^T staging (k-major), per layer

typedef unsigned long long u64;
typedef unsigned int u32;

// ---- packed f32x2 helpers (sm_100+; ptxas never auto-fuses these) ----
__device__ __forceinline__ void fma2(u64& d, u64 a, u64 b) {
    asm("fma.rn.f32x2 %0, %1, %2, %0;" : "+l"(d) : "l"(a), "l"(b));
}
__device__ __forceinline__ u64 pack2(float x) {
    u64 r; asm("mov.b64 %0, {%1, %1};" : "=l"(r) : "f"(x)); return r;
}
__device__ __forceinline__ float2 unpack2(u64 v) {
    float2 r; asm("mov.b64 {%0, %1}, %2;" : "=f"(r.x), "=f"(r.y) : "l"(v)); return r;
}
// broadcast a u64 from lane src to all lanes (2x shfl.b32)
__device__ __forceinline__ u64 shfl64(u64 v, int src) {
    u32 lo, hi;
    asm("mov.b64 {%0,%1}, %2;" : "=r"(lo), "=r"(hi) : "l"(v));
    lo = (u32)__shfl_sync(0xFFFFFFFFu, (int)lo, src);
    hi = (u32)__shfl_sync(0xFFFFFFFFu, (int)hi, src);
    u64 r;
    asm("mov.b64 %0, {%1,%2};" : "=l"(r) : "r"(lo), "r"(hi));
    return r;
}

__device__ __forceinline__ float fsigmoid(float x) {
    return __fdividef(1.f, 1.f + __expf(-x));
}
__device__ __forceinline__ float ftanh(float x) {
    return 1.f - __fdividef(2.f, __expf(2.f * x) + 1.f);
}

// ---- cp.async helpers ----
__device__ __forceinline__ void cp4(u32 saddr, const void* gaddr, bool valid) {
    int sz = valid ? 4 : 0;
    asm volatile("cp.async.ca.shared.global [%0], [%1], 4, %2;"
                 :: "r"(saddr), "l"(gaddr), "r"(sz) : "memory");
}
__device__ __forceinline__ void cp16(u32 saddr, const void* gaddr, bool valid) {
    int sz = valid ? 16 : 0;
    asm volatile("cp.async.cg.shared.global [%0], [%1], 16, %2;"
                 :: "r"(saddr), "l"(gaddr), "r"(sz) : "memory");
}
#define CP_COMMIT() asm volatile("cp.async.commit_group;" ::: "memory")

// =======================================================================
// One-time W transpose: g_wT[slot][k][c] = W[c][k]. grid K, block 384.
// =======================================================================
__global__ void transposeW(const float* __restrict__ W, int K, int slot) {
    int k = blockIdx.x, c = threadIdx.x;
    g_wT[slot][(size_t)k * GG + c] = W[(size_t)c * K + k];
}

// =======================================================================
// GEMM v3 (cp.async 3-stage, 32-row tiles, 2 CTAs/SM):
// g_gi[row][c] = X@W^T + bias. rows = 262144, N = 384, K in {153,128}.
// 256 threads, thread tile 4 rows x 6 col-PAIRS, packed f32x2 FMA.
// =======================================================================
#define XS_ST 512             // floats per xs stage
#define WS_ST (16 * GG)       // floats per ws stage
#define STG   (XS_ST + WS_ST)
#define GEMM_SMEM (3 * STG * (int)sizeof(float))

__global__ void __launch_bounds__(256) gemm384(
    const float* __restrict__ Xext, int useSeq, int K, int slot,
    const float* __restrict__ bias)
{
    const float* __restrict__ X = useSeq ? g_seq : Xext;
    const float* __restrict__ WT = g_wT[slot];
    extern __shared__ float sm[];
    u32 sbase = (u32)__cvta_generic_to_shared(sm);

    int tid = threadIdx.x;
    size_t row0 = (size_t)blockIdx.x * 32;
    int tr = (tid >> 5) * 4;     // thread row base within tile
    int tc = tid & 31;           // col-pair base; cols {2tc,2tc+1} + 64*j
    const int nch = (K + 15) / 16;

#define ISSUE(c, s) do {                                                      \
        int k0_ = (c) * 16;                                                   \
        _Pragma("unroll")                                                     \
        for (int i = 0; i < 2; i++) {                                         \
            int idx = tid + i * 256; int r = idx >> 4, kk = idx & 15;         \
            int k = k0_ + kk; bool v = (k < K);                               \
            size_t go = (row0 + r) * (size_t)K + (v ? k : 0);                 \
            cp4(sbase + ((s) * STG + r * 16 + kk) * 4, X + go, v);            \
        }                                                                     \
        _Pragma("unroll")                                                     \
        for (int i = 0; i < 6; i++) {                                         \
            int uix = tid + i * 256; int kk = uix / 96, cu = uix % 96;        \
            int k = k0_ + kk; bool v = (k < K);                               \
            cp16(sbase + ((s) * STG + XS_ST + kk * GG + cu * 4) * 4,          \
                 WT + (size_t)k * GG + cu * 4, v);                            \
        }                                                                     \
        CP_COMMIT();                                                          \
    } while (0)

    u64 acc[4][6];
#pragma unroll
    for (int r = 0; r < 4; r++)
#pragma unroll
        for (int j = 0; j < 6; j++) acc[r][j] = 0ull;

    ISSUE(0, 0);
    if (nch > 1) ISSUE(1, 1);

    for (int c = 0; c < nch; c++) {
        int s = c % 3;
        if (c + 2 < nch) {
            ISSUE(c + 2, (c + 2) % 3);
            asm volatile("cp.async.wait_group 2;" ::: "memory");
        } else if (c + 1 < nch) {
            asm volatile("cp.async.wait_group 1;" ::: "memory");
        } else {
            asm volatile("cp.async.wait_group 0;" ::: "memory");
        }
        __syncthreads();

        const float* xsp = sm + s * STG;
        const float* wsp = sm + s * STG + XS_ST;
#pragma unroll
        for (int kk = 0; kk < 16; kk++) {
            u64 wv[6];
#pragma unroll
            for (int j = 0; j < 6; j++)
                wv[j] = *(const u64*)&wsp[kk * GG + 2 * tc + 64 * j];
#pragma unroll
            for (int r = 0; r < 4; r++) {
                u64 xp = pack2(xsp[(tr + r) * 16 + kk]);  // uniform broadcast
#pragma unroll
                for (int j = 0; j < 6; j++)
                    fma2(acc[r][j], xp, wv[j]);
            }
        }
        __syncthreads();
    }

#pragma unroll
    for (int j = 0; j < 6; j++) {
        int c = 2 * tc + 64 * j;
        float2 bv = make_float2(bias[c], bias[c + 1]);
#pragma unroll
        for (int r = 0; r < 4; r++) {
            float2 v = unpack2(acc[r][j]);
            v.x += bv.x; v.y += bv.y;
            *(float2*)&g_gi[(row0 + tr + r) * (size_t)GG + c] = v;
        }
    }
#undef ISSUE
}

// =======================================================================
// GRU recurrence v6: v3 structure, but matvec h delivered via register
// cache + warp shuffle (crossbar relief). 128 CTAs x 8 batch rows;
// 384 threads. matvec team warps 0-3; gate team warps 4-11.
// =======================================================================
#define WK_STRIDE 385
#define GH_STRIDE 10
#define RECUR_SMEM ((128 * WK_STRIDE + 4 * 128 * 2 + 384 * GH_STRIDE) * (int)sizeof(float))

__global__ void __launch_bounds__(384) gru_recur(
    const float* __restrict__ Whh, const float* __restrict__ bhh, int writeSeq)
{
    extern __shared__ float smem[];
    float* wk   = smem;                        // [128][385]: wk[k*385+g] = Whh[g][k]
    float* hp   = smem + 128 * WK_STRIDE;      // [4][128] u64 row-pairs
    float* ghsh = hp + 4 * 128 * 2;            // [384][10]: gh[col][row] padded

    int tid = threadIdx.x;
    size_t b0 = (size_t)blockIdx.x * 8;

    for (int idx = tid; idx < GG * HH; idx += 384) {
        int g = idx >> 7, k = idx & 127;
        wk[k * WK_STRIDE + g] = Whh[idx];
    }
    for (int idx = tid; idx < 4 * 128 * 2; idx += 384) hp[idx] = 0.f;

    const bool mv = tid < 128;
    int col = tid;
    int lane = tid & 31;

    u64 bias2[3];
    if (mv) {
#pragma unroll
        for (int c = 0; c < 3; c++) bias2[c] = pack2(bhh[col + 128 * c]);
    }

    int t2 = tid - 128;
    int gr = t2 >> 5;
    int gl = t2 & 31;

    float hreg[4] = {0.f, 0.f, 0.f, 0.f};
    const float* gi_base = g_gi + ((b0 + gr) * TLEN) * (size_t)GG + gl;
    float* seq_base = g_seq + ((b0 + gr) * TLEN) * (size_t)HH + gl;

    __syncthreads();

    for (int t = 0; t < TLEN; t++) {
        float gi_v[12];
        if (!mv) {
            const float* gp = gi_base + (size_t)t * GG;
#pragma unroll
            for (int gidx = 0; gidx < 3; gidx++)
#pragma unroll
                for (int u = 0; u < 4; u++)
                    gi_v[gidx * 4 + u] = gp[gidx * 128 + u * 32];
        } else {
            // ---- coalesced h cache: lane holds hc[rp][m] = h-pair (rp, k=lane+32m)
            const u64* hp64 = (const u64*)hp;
            u64 hc[4][4];
#pragma unroll
            for (int rp = 0; rp < 4; rp++)
#pragma unroll
                for (int m = 0; m < 4; m++)
                    hc[rp][m] = hp64[rp * 128 + lane + 32 * m];

            u64 acc[4][3];
#pragma unroll
            for (int rp = 0; rp < 4; rp++)
#pragma unroll
                for (int c = 0; c < 3; c++) acc[rp][c] = bias2[c];

#pragma unroll
            for (int kp = 0; kp < 64; kp++) {
                const int k0 = 2 * kp, k1 = 2 * kp + 1;
                const int m0 = k0 >> 5, s0 = k0 & 31;
                const int m1 = k1 >> 5, s1 = k1 & 31;
                u64 wd0[3], wd1[3];
#pragma unroll
                for (int c = 0; c < 3; c++) {
                    wd0[c] = pack2(wk[k0 * WK_STRIDE + col + 128 * c]);
                    wd1[c] = pack2(wk[k1 * WK_STRIDE + col + 128 * c]);
                }
#pragma unroll
                for (int rp = 0; rp < 4; rp++) {
                    u64 h0 = shfl64(hc[rp][m0], s0);
                    u64 h1 = shfl64(hc[rp][m1], s1);
#pragma unroll
                    for (int c = 0; c < 3; c++) {
                        fma2(acc[rp][c], h0, wd0[c]);
                        fma2(acc[rp][c], h1, wd1[c]);
                    }
                }
            }
#pragma unroll
            for (int c = 0; c < 3; c++)
#pragma unroll
                for (int rp = 0; rp < 4; rp++)
                    *(u64*)(ghsh + (col + 128 * c) * GH_STRIDE + 2 * rp) = acc[rp][c];
        }
        __syncthreads();

        if (!mv) {
            int rsel = (gr >> 1) * 2 + (gr & 1);
            float hn[4];
#pragma unroll
            for (int u = 0; u < 4; u++) {
                int j = gl + 32 * u;
                float ghr = ghsh[j * GH_STRIDE + rsel];
                float ghz = ghsh[(j + 128) * GH_STRIDE + rsel];
                float ghn = ghsh[(j + 256) * GH_STRIDE + rsel];
                float r = fsigmoid(gi_v[u] + ghr);
                float z = fsigmoid(gi_v[4 + u] + ghz);
                float n = ftanh(gi_v[8 + u] + r * ghn);
                hn[u] = (1.f - z) * n + z * hreg[u];
                hreg[u] = hn[u];
            }
            int rp = gr >> 1, half = gr & 1;
#pragma unroll
            for (int u = 0; u < 4; u++) {
                int j = gl + 32 * u;
                hp[rp * 256 + 2 * j + half] = hn[u];
            }
            if (writeSeq) {
                float* sp = seq_base + (size_t)t * HH;
#pragma unroll
                for (int u = 0; u < 4; u++) sp[u * 32] = hn[u];
            }
        }
        __syncthreads();
    }

    if (!writeSeq && !mv) {
        float* hl = g_hlast + (b0 + gr) * HH + gl;
#pragma unroll
        for (int u = 0; u < 4; u++) hl[u * 32] = hreg[u];
    }
}

// =======================================================================
// Head: out[b] = sigmoid( relu(h_last[b] @ W1^T + b1) @ W2^T + b2 )
// =======================================================================
__global__ void __launch_bounds__(64) head_kernel(
    const float* __restrict__ W1, const float* __restrict__ b1,
    const float* __restrict__ W2, const float* __restrict__ b2,
    float* __restrict__ out)
{
    int b = blockIdx.x;
    int c = threadIdx.x;  // 0..63
    const float* hb = g_hlast + (size_t)b * HH;
    const float* wr = W1 + (size_t)c * HH;
    float acc = b1[c];
#pragma unroll
    for (int k = 0; k < HH; k += 4) {
        float4 hv = *(const float4*)(hb + k);
        float4 wv = *(const float4*)(wr + k);
        acc = fmaf(hv.x, wv.x, acc);
        acc = fmaf(hv.y, wv.y, acc);
        acc = fmaf(hv.z, wv.z, acc);
        acc = fmaf(hv.w, wv.w, acc);
    }
    float v = fmaxf(acc, 0.f) * W2[c];
    __shared__ float red[64];
    red[c] = v;
    __syncthreads();
    if (c == 0) {
        float s = b2[0];
#pragma unroll
        for (int i = 0; i < 64; i++) s += red[i];
        out[b] = 1.f / (1.f + expf(-s));
    }
}

// =======================================================================
extern "C" void kernel_launch(void* const* d_in, const int* in_sizes, int n_in,
                              void* d_out, int out_size)
{
    const float* x     = (const float*)d_in[0];
    const float* W_ih0 = (const float*)d_in[1];
    const float* W_hh0 = (const float*)d_in[2];
    const float* b_ih0 = (const float*)d_in[3];
    const float* b_hh0 = (const float*)d_in[4];
    const float* W_ih1 = (const float*)d_in[5];
    const float* W_hh1 = (const float*)d_in[6];
    const float* b_ih1 = (const float*)d_in[7];
    const float* b_hh1 = (const float*)d_in[8];
    const float* W1    = (const float*)d_in[9];
    const float* b1    = (const float*)d_in[10];
    const float* W2    = (const float*)d_in[11];
    const float* b2    = (const float*)d_in[12];
    float* out = (float*)d_out;

    cudaFuncSetAttribute(gru_recur, cudaFuncAttributeMaxDynamicSharedMemorySize,
                         RECUR_SMEM);
    cudaFuncSetAttribute(gemm384, cudaFuncAttributeMaxDynamicSharedMemorySize,
                         GEMM_SMEM);

    const int M_TILES = (BSZ * TLEN) / 32;  // 8192

    transposeW<<<153, GG>>>(W_ih0, 153, 0);
    transposeW<<<128, GG>>>(W_ih1, 128, 1);

    gemm384<<<M_TILES, 256, GEMM_SMEM>>>(x, 0, 153, 0, b_ih0);
    gru_recur<<<128, 384, RECUR_SMEM>>>(W_hh0, b_hh0, 1);
    gemm384<<<M_TILES, 256, GEMM_SMEM>>>(nullptr, 1, 128, 1, b_ih1);
    gru_recur<<<128, 384, RECUR_SMEM>>>(W_hh1, b_hh1, 0);
    head_kernel<<<BSZ, 64>>>(W1, b1, W2, b2, out);
}

// round 16
// speedup vs baseline: 1.3636x; 1.3636x over previous
#include <cuda_runtime.h>
#include <math.h>

#define BSZ  1024
#define TLEN 256
#define HH   128
#define GG   384   // 3*H

// -------- scratch (static device globals; no runtime allocation) --------
__device__ float g_gi[(size_t)BSZ * TLEN * GG];    // 402 MB, reused for gi0 then gi1
__device__ float g_seq[(size_t)BSZ * TLEN * HH];   // 134 MB, layer-0 output sequence
__device__ float g_hlast[(size_t)BSZ * HH];        // layer-1 final hidden
__device__ float g_wT[2][160 * GG];                // W^T staging (k-major), per layer

typedef unsigned long long u64;
typedef unsigned int u32;

// ---- packed f32x2 helpers (sm_100+; ptxas never auto-fuses these) ----
__device__ __forceinline__ void fma2(u64& d, u64 a, u64 b) {
    asm("fma.rn.f32x2 %0, %1, %2, %0;" : "+l"(d) : "l"(a), "l"(b));
}
__device__ __forceinline__ u64 pack2(float x) {
    u64 r; asm("mov.b64 %0, {%1, %1};" : "=l"(r) : "f"(x)); return r;
}
__device__ __forceinline__ float2 unpack2(u64 v) {
    float2 r; asm("mov.b64 {%0, %1}, %2;" : "=f"(r.x), "=f"(r.y) : "l"(v)); return r;
}

__device__ __forceinline__ float fsigmoid(float x) {
    return __fdividef(1.f, 1.f + __expf(-x));
}
__device__ __forceinline__ float ftanh(float x) {
    return 1.f - __fdividef(2.f, __expf(2.f * x) + 1.f);
}

// ---- cp.async helpers ----
__device__ __forceinline__ void cp4(u32 saddr, const void* gaddr, bool valid) {
    int sz = valid ? 4 : 0;
    asm volatile("cp.async.ca.shared.global [%0], [%1], 4, %2;"
                 :: "r"(saddr), "l"(gaddr), "r"(sz) : "memory");
}
__device__ __forceinline__ void cp16(u32 saddr, const void* gaddr, bool valid) {
    int sz = valid ? 16 : 0;
    asm volatile("cp.async.cg.shared.global [%0], [%1], 16, %2;"
                 :: "r"(saddr), "l"(gaddr), "r"(sz) : "memory");
}
#define CP_COMMIT() asm volatile("cp.async.commit_group;" ::: "memory")

// =======================================================================
// One-time W transpose: g_wT[slot][k][c] = W[c][k]. grid K, block 384.
// =======================================================================
__global__ void transposeW(const float* __restrict__ W, int K, int slot) {
    int k = blockIdx.x, c = threadIdx.x;
    g_wT[slot][(size_t)k * GG + c] = W[(size_t)c * K + k];
}

// =======================================================================
// GEMM (cp.async 3-stage, 32-row tiles, 2 CTAs/SM) — measured config:
// g_gi[row][c] = X@W^T + bias. rows = 262144, N = 384, K in {153,128}.
// 256 threads, thread tile 4 rows x 6 col-PAIRS, packed f32x2 FMA.
// =======================================================================
#define XS_ST 512             // floats per xs stage
#define WS_ST (16 * GG)       // floats per ws stage
#define STG   (XS_ST + WS_ST)
#define GEMM_SMEM (3 * STG * (int)sizeof(float))

__global__ void __launch_bounds__(256) gemm384(
    const float* __restrict__ Xext, int useSeq, int K, int slot,
    const float* __restrict__ bias)
{
    const float* __restrict__ X = useSeq ? g_seq : Xext;
    const float* __restrict__ WT = g_wT[slot];
    extern __shared__ float sm[];
    u32 sbase = (u32)__cvta_generic_to_shared(sm);

    int tid = threadIdx.x;
    size_t row0 = (size_t)blockIdx.x * 32;
    int tr = (tid >> 5) * 4;     // thread row base within tile
    int tc = tid & 31;           // col-pair base; cols {2tc,2tc+1} + 64*j
    const int nch = (K + 15) / 16;

#define ISSUE(c, s) do {                                                      \
        int k0_ = (c) * 16;                                                   \
        _Pragma("unroll")                                                     \
        for (int i = 0; i < 2; i++) {                                         \
            int idx = tid + i * 256; int r = idx >> 4, kk = idx & 15;         \
            int k = k0_ + kk; bool v = (k < K);                               \
            size_t go = (row0 + r) * (size_t)K + (v ? k : 0);                 \
            cp4(sbase + ((s) * STG + r * 16 + kk) * 4, X + go, v);            \
        }                                                                     \
        _Pragma("unroll")                                                     \
        for (int i = 0; i < 6; i++) {                                         \
            int uix = tid + i * 256; int kk = uix / 96, cu = uix % 96;        \
            int k = k0_ + kk; bool v = (k < K);                               \
            cp16(sbase + ((s) * STG + XS_ST + kk * GG + cu * 4) * 4,          \
                 WT + (size_t)k * GG + cu * 4, v);                            \
        }                                                                     \
        CP_COMMIT();                                                          \
    } while (0)

    u64 acc[4][6];
#pragma unroll
    for (int r = 0; r < 4; r++)
#pragma unroll
        for (int j = 0; j < 6; j++) acc[r][j] = 0ull;

    ISSUE(0, 0);
    if (nch > 1) ISSUE(1, 1);

    for (int c = 0; c < nch; c++) {
        int s = c % 3;
        if (c + 2 < nch) {
            ISSUE(c + 2, (c + 2) % 3);
            asm volatile("cp.async.wait_group 2;" ::: "memory");
        } else if (c + 1 < nch) {
            asm volatile("cp.async.wait_group 1;" ::: "memory");
        } else {
            asm volatile("cp.async.wait_group 0;" ::: "memory");
        }
        __syncthreads();

        const float* xsp = sm + s * STG;
        const float* wsp = sm + s * STG + XS_ST;
#pragma unroll
        for (int kk = 0; kk < 16; kk++) {
            u64 wv[6];
#pragma unroll
            for (int j = 0; j < 6; j++)
                wv[j] = *(const u64*)&wsp[kk * GG + 2 * tc + 64 * j];
#pragma unroll
            for (int r = 0; r < 4; r++) {
                u64 xp = pack2(xsp[(tr + r) * 16 + kk]);  // uniform broadcast
#pragma unroll
                for (int j = 0; j < 6; j++)
                    fma2(acc[r][j], xp, wv[j]);
            }
        }
        __syncthreads();
    }

#pragma unroll
    for (int j = 0; j < 6; j++) {
        int c = 2 * tc + 64 * j;
        float2 bv = make_float2(bias[c], bias[c + 1]);
#pragma unroll
        for (int r = 0; r < 4; r++) {
            float2 v = unpack2(acc[r][j]);
            v.x += bv.x; v.y += bv.y;
            *(float2*)&g_gi[(row0 + tr + r) * (size_t)GG + c] = v;
        }
    }
#undef ISSUE
}

// =======================================================================
// GRU recurrence v7: v3 dataflow, matvec doubled via ROW-split.
// 128 CTAs x 8 batch rows; 512 threads.
//  - matvec team: warps 0-7 (256 thr). thread = col (tid&127) x row-half
//    (tid>>7): 2 row-pairs each, COMPLETE dot products (no partial sums).
//    W read twice per step (once per half); staging identical to v3.
//  - gate team: warps 8-15 (256 thr) — byte-identical to v3's gate phase.
// smem: wk[128][385] + hp[4][256] + ghsh[384][10] = 216.6 KB
// =======================================================================
#define WK_STRIDE 385
#define GH_STRIDE 10
#define RECUR_SMEM ((128 * WK_STRIDE + 4 * 128 * 2 + 384 * GH_STRIDE) * (int)sizeof(float))

__global__ void __launch_bounds__(512) gru_recur(
    const float* __restrict__ Whh, const float* __restrict__ bhh, int writeSeq)
{
    extern __shared__ float smem[];
    float* wk   = smem;                        // [128][385]: wk[k*385+g] = Whh[g][k]
    float* hp   = smem + 128 * WK_STRIDE;      // [4][128] u64 row-pairs
    float* ghsh = hp + 4 * 128 * 2;            // [384][10]: gh[col][row] padded

    int tid = threadIdx.x;
    size_t b0 = (size_t)blockIdx.x * 8;

    for (int idx = tid; idx < GG * HH; idx += 512) {
        int g = idx >> 7, k = idx & 127;
        wk[k * WK_STRIDE + g] = Whh[idx];
    }
    for (int idx = tid; idx < 4 * 128 * 2; idx += 512) hp[idx] = 0.f;

    const bool mv = tid < 256;                 // matvec team
    const int col  = tid & 127;                // cols col, col+128, col+256
    const int rp0  = ((tid >> 7) & 1) * 2;     // row-pairs rp0, rp0+1

    u64 bias2[3];
    if (mv) {
#pragma unroll
        for (int c = 0; c < 3; c++) bias2[c] = pack2(bhh[col + 128 * c]);
    }

    // gate team mapping (identical to v3, shifted by 256)
    int t2 = tid - 256;
    int gr = (t2 >> 5) & 7;
    int gl = t2 & 31;

    float hreg[4] = {0.f, 0.f, 0.f, 0.f};
    const float* gi_base = g_gi + ((b0 + gr) * TLEN) * (size_t)GG + gl;
    float* seq_base = g_seq + ((b0 + gr) * TLEN) * (size_t)HH + gl;

    __syncthreads();

    for (int t = 0; t < TLEN; t++) {
        float gi_v[12];
        if (!mv) {
            // gi prefetch: LDGs issue here, hidden under the matvec phase
            const float* gp = gi_base + (size_t)t * GG;
#pragma unroll
            for (int gidx = 0; gidx < 3; gidx++)
#pragma unroll
                for (int u = 0; u < 4; u++)
                    gi_v[gidx * 4 + u] = gp[gidx * 128 + u * 32];
        } else {
            u64 acc[2][3];
#pragma unroll
            for (int q = 0; q < 2; q++)
#pragma unroll
                for (int c = 0; c < 3; c++) acc[q][c] = bias2[c];

#pragma unroll 4
            for (int k = 0; k < HH; k += 2) {
                u64 wd0[3], wd1[3];
#pragma unroll
                for (int c = 0; c < 3; c++) {
                    wd0[c] = pack2(wk[k * WK_STRIDE + col + 128 * c]);
                    wd1[c] = pack2(wk[(k + 1) * WK_STRIDE + col + 128 * c]);
                }
#pragma unroll
                for (int q = 0; q < 2; q++) {
                    // {h_2rp(k),h_2rp+1(k),h_2rp(k+1),h_2rp+1(k+1)} broadcast
                    ulonglong2 h2 = *(const ulonglong2*)(hp + (rp0 + q) * 256 + 2 * k);
#pragma unroll
                    for (int c = 0; c < 3; c++) {
                        fma2(acc[q][c], h2.x, wd0[c]);
                        fma2(acc[q][c], h2.y, wd1[c]);
                    }
                }
            }
#pragma unroll
            for (int c = 0; c < 3; c++)
#pragma unroll
                for (int q = 0; q < 2; q++)
                    *(u64*)(ghsh + (col + 128 * c) * GH_STRIDE + 2 * (rp0 + q)) = acc[q][c];
        }
        __syncthreads();

        if (!mv) {
            int rsel = (gr >> 1) * 2 + (gr & 1);
            float hn[4];
#pragma unroll
            for (int u = 0; u < 4; u++) {
                int j = gl + 32 * u;
                float ghr = ghsh[j * GH_STRIDE + rsel];
                float ghz = ghsh[(j + 128) * GH_STRIDE + rsel];
                float ghn = ghsh[(j + 256) * GH_STRIDE + rsel];
                float r = fsigmoid(gi_v[u] + ghr);
                float z = fsigmoid(gi_v[4 + u] + ghz);
                float n = ftanh(gi_v[8 + u] + r * ghn);
                hn[u] = (1.f - z) * n + z * hreg[u];
                hreg[u] = hn[u];
            }
            int rp = gr >> 1, half = gr & 1;
#pragma unroll
            for (int u = 0; u < 4; u++) {
                int j = gl + 32 * u;
                hp[rp * 256 + 2 * j + half] = hn[u];
            }
            if (writeSeq) {
                float* sp = seq_base + (size_t)t * HH;
#pragma unroll
                for (int u = 0; u < 4; u++) sp[u * 32] = hn[u];
            }
        }
        __syncthreads();
    }

    if (!writeSeq && !mv) {
        float* hl = g_hlast + (b0 + gr) * HH + gl;
#pragma unroll
        for (int u = 0; u < 4; u++) hl[u * 32] = hreg[u];
    }
}

// =======================================================================
// Head: out[b] = sigmoid( relu(h_last[b] @ W1^T + b1) @ W2^T + b2 )
// =======================================================================
__global__ void __launch_bounds__(64) head_kernel(
    const float* __restrict__ W1, const float* __restrict__ b1,
    const float* __restrict__ W2, const float* __restrict__ b2,
    float* __restrict__ out)
{
    int b = blockIdx.x;
    int c = threadIdx.x;  // 0..63
    const float* hb = g_hlast + (size_t)b * HH;
    const float* wr = W1 + (size_t)c * HH;
    float acc = b1[c];
#pragma unroll
    for (int k = 0; k < HH; k += 4) {
        float4 hv = *(const float4*)(hb + k);
        float4 wv = *(const float4*)(wr + k);
        acc = fmaf(hv.x, wv.x, acc);
        acc = fmaf(hv.y, wv.y, acc);
        acc = fmaf(hv.z, wv.z, acc);
        acc = fmaf(hv.w, wv.w, acc);
    }
    float v = fmaxf(acc, 0.f) * W2[c];
    __shared__ float red[64];
    red[c] = v;
    __syncthreads();
    if (c == 0) {
        float s = b2[0];
#pragma unroll
        for (int i = 0; i < 64; i++) s += red[i];
        out[b] = 1.f / (1.f + expf(-s));
    }
}

// =======================================================================
extern "C" void kernel_launch(void* const* d_in, const int* in_sizes, int n_in,
                              void* d_out, int out_size)
{
    const float* x     = (const float*)d_in[0];
    const float* W_ih0 = (const float*)d_in[1];
    const float* W_hh0 = (const float*)d_in[2];
    const float* b_ih0 = (const float*)d_in[3];
    const float* b_hh0 = (const float*)d_in[4];
    const float* W_ih1 = (const float*)d_in[5];
    const float* W_hh1 = (const float*)d_in[6];
    const float* b_ih1 = (const float*)d_in[7];
    const float* b_hh1 = (const float*)d_in[8];
    const float* W1    = (const float*)d_in[9];
    const float* b1    = (const float*)d_in[10];
    const float* W2    = (const float*)d_in[11];
    const float* b2    = (const float*)d_in[12];
    float* out = (float*)d_out;

    cudaFuncSetAttribute(gru_recur, cudaFuncAttributeMaxDynamicSharedMemorySize,
                         RECUR_SMEM);
    cudaFuncSetAttribute(gemm384, cudaFuncAttributeMaxDynamicSharedMemorySize,
                         GEMM_SMEM);

    const int M_TILES = (BSZ * TLEN) / 32;  // 8192

    transposeW<<<153, GG>>>(W_ih0, 153, 0);
    transposeW<<<128, GG>>>(W_ih1, 128, 1);

    gemm384<<<M_TILES, 256, GEMM_SMEM>>>(x, 0, 153, 0, b_ih0);
    gru_recur<<<128, 512, RECUR_SMEM>>>(W_hh0, b_hh0, 1);
    gemm384<<<M_TILES, 256, GEMM_SMEM>>>(nullptr, 1, 128, 1, b_ih1);
    gru_recur<<<128, 512, RECUR_SMEM>>>(W_hh1, b_hh1, 0);
    head_kernel<<<BSZ, 64>>>(W1, b1, W2, b2, out);
}